// round 8
// baseline (speedup 1.0000x reference)
#include <cuda_runtime.h>

// GRUAdder: B = 1048576, T=4, I=2, H=16.
// 8 lanes per row; lane q owns h[2q],h[2q+1] and gates {2q,2q+1} of r/z/n.
// f32x2 accumulators are split by k-PARITY: acc_j = (sum_even_k, sum_odd_k),
// so the broadcast operand for k-pair kp is the owner lane's packed h register
// (shfl 64-bit, used directly by ffma2 -- no packing movs in the inner loop).
// Weights register-resident: 48 ull per lane. 2 rows in flight per thread.

#define TT 4
#define II 2
#define HH 16
#define LROWS 8   // iterations; rows per warp = 8 * LROWS = 64

typedef unsigned long long ull;

__device__ __forceinline__ ull ffma2(ull a, ull b, ull c) {
    ull d;
    asm("fma.rn.f32x2 %0, %1, %2, %3;" : "=l"(d) : "l"(a), "l"(b), "l"(c));
    return d;
}
__device__ __forceinline__ ull pk2(float lo, float hi) {
    ull r;
    asm("mov.b64 %0, {%1, %2};" : "=l"(r) : "f"(lo), "f"(hi));
    return r;
}
__device__ __forceinline__ void upk2(float& lo, float& hi, ull v) {
    asm("mov.b64 {%0, %1}, %2;" : "=f"(lo), "=f"(hi) : "l"(v));
}
__device__ __forceinline__ float hadd2(ull v) {
    float lo, hi;
    upk2(lo, hi, v);
    return lo + hi;
}
__device__ __forceinline__ float fsig(float x) {
    float e, r;
    asm("ex2.approx.f32 %0, %1;" : "=f"(e) : "f"(-1.4426950408889634f * x));
    asm("rcp.approx.f32 %0, %1;" : "=f"(r) : "f"(1.0f + e));
    return r;
}
__device__ __forceinline__ float ftanh_fast(float x) {
    float e, r;
    asm("ex2.approx.f32 %0, %1;" : "=f"(e) : "f"(-2.8853900817779268f * x));
    asm("rcp.approx.f32 %0, %1;" : "=f"(r) : "f"(1.0f + e));
    return 2.0f * r - 1.0f;
}

__global__ void __launch_bounds__(128) gru_adder_kernel(
    const float* __restrict__ x,        // [B, 4, 2]
    const float* __restrict__ w_ih,     // [48, 2]
    const float* __restrict__ w_hh,     // [48, 16]
    const float* __restrict__ b_ih,     // [48]
    const float* __restrict__ b_hh,     // [48]
    const float* __restrict__ w_sum,    // [1, 16]
    const float* __restrict__ b_sum,    // [1]
    const float* __restrict__ w_carry,  // [1, 16]
    const float* __restrict__ b_carry,  // [1]
    float* __restrict__ hid,            // [B, 4, 16]
    float* __restrict__ sumo,           // [B, 4]
    float* __restrict__ carryo,         // [B]
    float* __restrict__ olog,           // [B, 5]
    long long B)
{
    // Slots s: 0=r-even,1=r-odd,2=z-even,3=z-odd,4=n-even,5=n-odd.
    // Gate of (s,q): j = (s>>1)*16 + 2*q + (s&1).
    // sh_wp[(kp*6+s)*8+q] = ( w_hh[j][2kp], w_hh[j][2kp+1] )
    __shared__ __align__(16) ull sh_wp[8 * 6 * 8];
    __shared__ __align__(16) ull sh_uih[6 * 8];   // (w_ih[j][0], w_ih[j][1])
    __shared__ __align__(16) ull sh_bias[6 * 8];  // (bias_j, 0)
    __shared__ __align__(16) float sh_bin[16];    // b_ih for n gates
    __shared__ __align__(16) ull sh_ws[8], sh_wc[8];
    __shared__ float sh_bs, sh_bc;

    const int tidb = threadIdx.x;
    for (int idx = tidb; idx < 384; idx += 128) {
        int kp = idx / 48, rem = idx % 48, s = rem / 8, qq = rem % 8;
        int j = (s >> 1) * 16 + 2 * qq + (s & 1);
        sh_wp[idx] = pk2(w_hh[j * HH + 2 * kp], w_hh[j * HH + 2 * kp + 1]);
    }
    if (tidb < 48) {
        int s = tidb / 8, qq = tidb % 8;
        int j = (s >> 1) * 16 + 2 * qq + (s & 1);
        sh_uih[tidb] = pk2(w_ih[j * II + 0], w_ih[j * II + 1]);
        float bb = (s < 4) ? (b_ih[j] + b_hh[j]) : b_hh[j];
        sh_bias[tidb] = pk2(bb, 0.0f);
    }
    if (tidb < 16) sh_bin[tidb] = b_ih[32 + tidb];
    if (tidb < 8) {
        sh_ws[tidb] = pk2(w_sum[2 * tidb],   w_sum[2 * tidb + 1]);
        sh_wc[tidb] = pk2(w_carry[2 * tidb], w_carry[2 * tidb + 1]);
        if (tidb == 0) { sh_bs = b_sum[0]; sh_bc = b_carry[0]; }
    }
    __syncthreads();

    const int lane    = tidb & 31;
    const int q       = lane & 7;
    const int grp     = lane >> 3;
    const int grpbase = lane & 24;

    // Register-resident weights: 48 ull.
    ull wv[8][6];
    #pragma unroll
    for (int kp = 0; kp < 8; kp++)
        #pragma unroll
        for (int s = 0; s < 6; s++)
            wv[kp][s] = sh_wp[(kp * 6 + s) * 8 + q];

    const ull uR0 = sh_uih[0 * 8 + q], uR1 = sh_uih[1 * 8 + q];
    const ull uZ0 = sh_uih[2 * 8 + q], uZ1 = sh_uih[3 * 8 + q];
    const ull uN0 = sh_uih[4 * 8 + q], uN1 = sh_uih[5 * 8 + q];
    const ull bR0 = sh_bias[0 * 8 + q], bR1 = sh_bias[1 * 8 + q];
    const ull bZ0 = sh_bias[2 * 8 + q], bZ1 = sh_bias[3 * 8 + q];
    const ull bN0 = sh_bias[4 * 8 + q], bN1 = sh_bias[5 * 8 + q];
    float win00, win01, win10, win11;
    upk2(win00, win01, uN0);
    upk2(win10, win11, uN1);
    const float biN0 = sh_bin[2 * q], biN1 = sh_bin[2 * q + 1];
    float wsl, wsh, wcl, wch;
    upk2(wsl, wsh, sh_ws[q]);
    upk2(wcl, wch, sh_wc[q]);
    const float bs = sh_bs, bc = sh_bc;

    const int  warp_global = blockIdx.x * (blockDim.x >> 5) + (tidb >> 5);
    const long long rowbase0 = (long long)warp_global * (8 * LROWS);
    if (rowbase0 >= B) return;

    #pragma unroll 1
    for (int it = 0; it < LROWS; it++) {
        const long long rowA = rowbase0 + it * 8 + grp;
        const long long rowB = rowA + 4;

        ull hApk = 0, hBpk = 0;   // (h[2q], h[2q+1]) packed

        #pragma unroll
        for (int t = 0; t < TT; t++) {
            const float2 xA = *reinterpret_cast<const float2*>(x + rowA * (TT*II) + t*II);
            const float2 xB = *reinterpret_cast<const float2*>(x + rowB * (TT*II) + t*II);
            const ull xpA = pk2(xA.x, xA.y);
            const ull xpB = pk2(xB.x, xB.y);

            ull aR0A = ffma2(uR0, xpA, bR0), aR1A = ffma2(uR1, xpA, bR1);
            ull aZ0A = ffma2(uZ0, xpA, bZ0), aZ1A = ffma2(uZ1, xpA, bZ1);
            ull aN0A = bN0,                  aN1A = bN1;
            ull aR0B = ffma2(uR0, xpB, bR0), aR1B = ffma2(uR1, xpB, bR1);
            ull aZ0B = ffma2(uZ0, xpB, bZ0), aZ1B = ffma2(uZ1, xpB, bZ1);
            ull aN0B = bN0,                  aN1B = bN1;
            const float giA0 = fmaf(win01, xA.y, fmaf(win00, xA.x, biN0));
            const float giA1 = fmaf(win11, xA.y, fmaf(win10, xA.x, biN1));
            const float giB0 = fmaf(win01, xB.y, fmaf(win00, xB.x, biN0));
            const float giB1 = fmaf(win11, xB.y, fmaf(win10, xB.x, biN1));

            // matvec over 8 k-pairs; broadcast = owner's packed h, no repack
            #pragma unroll
            for (int kp = 0; kp < 8; kp++) {
                const ull hbA = __shfl_sync(0xffffffffu, hApk, grpbase | kp);
                const ull hbB = __shfl_sync(0xffffffffu, hBpk, grpbase | kp);
                aR0A = ffma2(wv[kp][0], hbA, aR0A);
                aR1A = ffma2(wv[kp][1], hbA, aR1A);
                aZ0A = ffma2(wv[kp][2], hbA, aZ0A);
                aZ1A = ffma2(wv[kp][3], hbA, aZ1A);
                aN0A = ffma2(wv[kp][4], hbA, aN0A);
                aN1A = ffma2(wv[kp][5], hbA, aN1A);
                aR0B = ffma2(wv[kp][0], hbB, aR0B);
                aR1B = ffma2(wv[kp][1], hbB, aR1B);
                aZ0B = ffma2(wv[kp][2], hbB, aZ0B);
                aZ1B = ffma2(wv[kp][3], hbB, aZ1B);
                aN0B = ffma2(wv[kp][4], hbB, aN0B);
                aN1B = ffma2(wv[kp][5], hbB, aN1B);
            }

            // epilogue row A
            float hA0, hA1, hB0, hB1;
            {
                float hp0, hp1;
                upk2(hp0, hp1, hApk);
                float r0 = fsig(hadd2(aR0A));
                float r1 = fsig(hadd2(aR1A));
                float z0 = fsig(hadd2(aZ0A));
                float z1 = fsig(hadd2(aZ1A));
                float n0 = ftanh_fast(giA0 + r0 * hadd2(aN0A));
                float n1 = ftanh_fast(giA1 + r1 * hadd2(aN1A));
                hA0 = n0 + z0 * (hp0 - n0);
                hA1 = n1 + z1 * (hp1 - n1);
                hApk = pk2(hA0, hA1);
            }
            // epilogue row B
            {
                float hp0, hp1;
                upk2(hp0, hp1, hBpk);
                float r0 = fsig(hadd2(aR0B));
                float r1 = fsig(hadd2(aR1B));
                float z0 = fsig(hadd2(aZ0B));
                float z1 = fsig(hadd2(aZ1B));
                float n0 = ftanh_fast(giB0 + r0 * hadd2(aN0B));
                float n1 = ftanh_fast(giB1 + r1 * hadd2(aN1B));
                hB0 = n0 + z0 * (hp0 - n0);
                hB1 = n1 + z1 * (hp1 - n1);
                hBpk = pk2(hB0, hB1);
            }

            // sum head: 8-lane butterfly all-reduce
            float spA = hA0 * wsl + hA1 * wsh;
            float spB = hB0 * wsl + hB1 * wsh;
            spA += __shfl_xor_sync(0xffffffffu, spA, 1);
            spA += __shfl_xor_sync(0xffffffffu, spA, 2);
            spA += __shfl_xor_sync(0xffffffffu, spA, 4);
            spB += __shfl_xor_sync(0xffffffffu, spB, 1);
            spB += __shfl_xor_sync(0xffffffffu, spB, 2);
            spB += __shfl_xor_sync(0xffffffffu, spB, 4);

            if (hid) {
                *reinterpret_cast<float2*>(hid + rowA * (TT*HH) + t*HH + 2*q) =
                    make_float2(hA0, hA1);
                *reinterpret_cast<float2*>(hid + rowB * (TT*HH) + t*HH + 2*q) =
                    make_float2(hB0, hB1);
            }
            if (q == 0) {
                if (sumo) {
                    sumo[rowA * TT + t] = bs + spA;
                    sumo[rowB * TT + t] = bs + spB;
                }
            } else if (q == 1) {
                if (olog) {
                    olog[rowA * (TT+1) + t] = bs + spA;
                    olog[rowB * (TT+1) + t] = bs + spB;
                }
            }
        }

        // carry head
        float hA0, hA1, hB0, hB1;
        upk2(hA0, hA1, hApk);
        upk2(hB0, hB1, hBpk);
        float cpA = hA0 * wcl + hA1 * wch;
        float cpB = hB0 * wcl + hB1 * wch;
        cpA += __shfl_xor_sync(0xffffffffu, cpA, 1);
        cpA += __shfl_xor_sync(0xffffffffu, cpA, 2);
        cpA += __shfl_xor_sync(0xffffffffu, cpA, 4);
        cpB += __shfl_xor_sync(0xffffffffu, cpB, 1);
        cpB += __shfl_xor_sync(0xffffffffu, cpB, 2);
        cpB += __shfl_xor_sync(0xffffffffu, cpB, 4);
        if (q == 2) {
            if (carryo) {
                carryo[rowA] = bc + cpA;
                carryo[rowB] = bc + cpB;
            }
        } else if (q == 3) {
            if (olog) {
                olog[rowA * (TT+1) + TT] = bc + cpA;
                olog[rowB * (TT+1) + TT] = bc + cpB;
            }
        }
    }
}

extern "C" void kernel_launch(void* const* d_in, const int* in_sizes, int n_in,
                              void* d_out, int out_size) {
    const float* x       = (const float*)d_in[0];
    const float* w_ih    = (const float*)d_in[1];
    const float* w_hh    = (const float*)d_in[2];
    const float* b_ih    = (const float*)d_in[3];
    const float* b_hh    = (const float*)d_in[4];
    const float* w_sum   = (const float*)d_in[5];
    const float* b_sum   = (const float*)d_in[6];
    const float* w_carry = (const float*)d_in[7];
    const float* b_carry = (const float*)d_in[8];

    long long B = (long long)in_sizes[0] / (TT * II);
    float* out = (float*)d_out;
    long long os = (long long)out_size;

    // Output layout: concatenation of flattened (hidden_table, sum_logits,
    // carry_logit, output_logits) = 74 floats per row; fall back otherwise.
    float *hid = nullptr, *sum = nullptr, *car = nullptr, *olog = nullptr;
    if (os >= B * 74) {
        hid = out; sum = out + B * 64; car = out + B * 68; olog = out + B * 69;
    } else if (os >= B * 64) {
        hid = out;
    } else if (os >= B * 5) {
        olog = out;
    } else if (os >= B * 4) {
        sum = out;
    } else {
        car = out;
    }

    const int threads = 128;                       // 4 warps per CTA
    const long long rows_per_warp = 8 * LROWS;     // 64
    long long warps = (B + rows_per_warp - 1) / rows_per_warp;
    long long ctas  = (warps + 3) / 4;
    gru_adder_kernel<<<(int)ctas, threads>>>(x, w_ih, w_hh, b_ih, b_hh,
                                             w_sum, b_sum, w_carry, b_carry,
                                             hid, sum, car, olog, B);
}